// round 5
// baseline (speedup 1.0000x reference)
#include <cuda_runtime.h>
#include <cuda_bf16.h>

// TransferMatrixMethod: B=256, L=64 (62 interior), W=512.
// Layer matrices [[a, ib],[ic, d]] (real a,b,c,d) closed under multiplication.
// Track A,B,C,Dt(=-D). f32x2 lanes = 2 adjacent wavelengths; each thread runs
// TWO independent packed chains (4 wavelengths) for ILP=2.
//
// 4-way layer split: layers padded to 64 with identity layers (nd=0 -> sin=0,
// cos=1 -> exact no-op). Lane = (h<<3)|c: h=0..3 owns layers [16h,16h+16).
// Combine via 2 shuffle rounds (lane xor 8, then xor 16):
//   Z = L*R:  Z_A = LA*RA - LB*RC          Z_B = LA*RB - LB*RDt
//             Z_C = LC*RA - LDt*RC         Z_Dt = -LDt*RDt + LC*RB
//   (using Dt=-D everywhere; verified against the R4 passing kernel's algebra)
//
// Epilogue: E=(A+1e-9)+i*B*nsub, H=D*nsub+i*C,
//   r=(nin*E-H)/(nin*E+H), R=|num|^2/|den|^2 -> one division per point.

#define LTOT 64
#define WDIM 512
#define TPB  128

typedef unsigned long long u64;

__device__ __forceinline__ u64 pack2(float lo, float hi) {
    u64 r;
    asm("mov.b64 %0, {%1, %2};" : "=l"(r) : "f"(lo), "f"(hi));
    return r;
}
__device__ __forceinline__ void unpack2(float& lo, float& hi, u64 v) {
    asm("mov.b64 {%0, %1}, %2;" : "=f"(lo), "=f"(hi) : "l"(v));
}
__device__ __forceinline__ u64 mul2(u64 a, u64 b) {
    u64 r;
    asm("mul.rn.f32x2 %0, %1, %2;" : "=l"(r) : "l"(a), "l"(b));
    return r;
}
__device__ __forceinline__ u64 fma2(u64 a, u64 b, u64 c) {
    u64 r;
    asm("fma.rn.f32x2 %0, %1, %2, %3;" : "=l"(r) : "l"(a), "l"(b), "l"(c));
    return r;
}
__device__ __forceinline__ u64 neg2(u64 a) {
    return a ^ 0x8000000080000000ULL;
}

__device__ __forceinline__ void combine(u64& A, u64& B, u64& C, u64& Dt,
                                        int xm, bool upper)
{
    const unsigned FULL = 0xffffffffu;
    u64 pA  = __shfl_xor_sync(FULL, A,  xm);
    u64 pB  = __shfl_xor_sync(FULL, B,  xm);
    u64 pC  = __shfl_xor_sync(FULL, C,  xm);
    u64 pDt = __shfl_xor_sync(FULL, Dt, xm);

    u64 LA  = upper ? pA  : A;   u64 RA  = upper ? A  : pA;
    u64 LB  = upper ? pB  : B;   u64 RB  = upper ? B  : pB;
    u64 LC  = upper ? pC  : C;   u64 RC  = upper ? C  : pC;
    u64 LDt = upper ? pDt : Dt;  u64 RDt = upper ? Dt : pDt;

    u64 nLB  = neg2(LB);
    u64 nLDt = neg2(LDt);

    u64 zA  = fma2(nLB,  RC,  mul2(LA, RA));   // LA*RA - LB*RC
    u64 zB  = fma2(nLB,  RDt, mul2(LA, RB));   // LA*RB - LB*RDt
    u64 zC  = fma2(nLDt, RC,  mul2(LC, RA));   // LC*RA - LDt*RC
    u64 zDt = fma2(nLDt, RDt, mul2(LC, RB));   // -LDt*RDt + LC*RB
    A = zA; B = zB; C = zC; Dt = zDt;
}

__device__ __forceinline__ void epi2(u64 A, u64 B, u64 C, u64 Dt,
                                     float nin, float nsub, float* R)
{
    float A0, A1, B0, B1, C0, C1, Dt0, Dt1;
    unpack2(A0, A1, A);
    unpack2(B0, B1, B);
    unpack2(C0, C1, C);
    unpack2(Dt0, Dt1, Dt);
    #pragma unroll
    for (int i = 0; i < 2; ++i) {
        const float a  = i ? A1 : A0;
        const float bb = i ? B1 : B0;
        const float c  = i ? C1 : C0;
        const float d  = -(i ? Dt1 : Dt0);

        const float Er = a + 1e-9f;
        const float Ei = bb * nsub;
        const float Hr = d * nsub;
        const float Hi = c;

        const float numr = fmaf(nin, Er, -Hr);
        const float numi = fmaf(nin, Ei, -Hi);
        const float denr = fmaf(nin, Er,  Hr);
        const float deni = fmaf(nin, Ei,  Hi);

        const float num2 = fmaf(numr, numr, numi * numi);
        const float den2 = fmaf(denr, denr, deni * deni);
        R[i] = num2 / den2;
    }
}

__global__ __launch_bounds__(TPB)
void tmm_kernel(const float* __restrict__ n_layers,
                const float* __restrict__ d_layers,
                const float* __restrict__ wavelengths,
                float* __restrict__ out)
{
    const int b    = blockIdx.x >> 2;        // 0..255
    const int q    = blockIdx.x & 3;         // quarter of wavelength axis
    const int t    = threadIdx.x;            // 0..127
    const int lane = t & 31;
    const int wrp  = t >> 5;
    const int h    = lane >> 3;              // layer-split index, 0..3
    const int c    = lane & 7;               // chain within warp
    const int chain = wrp * 8 + c;           // 0..31 in block
    const int w0   = q * 128 + chain * 4;    // first of 4 wavelengths

    // padded layer tables: index = 17*h + j, j in [0,16); layers 62,63 = identity
    __shared__ float s_nd[68];
    __shared__ u64   s_n2[68];
    __shared__ u64   s_mr2[68];
    __shared__ float s_nin, s_nsub;

    if (t < 64) {
        const int hh = t >> 4, j = t & 15, idx = hh * 17 + j;
        float nv = 1.0f, ndv = 0.0f, mr = -1.0f;
        if (t < 62) {
            nv = n_layers[b * LTOT + t + 1];
            float dv = d_layers[b * LTOT + t + 1];
            ndv = nv * dv;
            mr = -1.0f / (nv + 1e-8f);
        }
        s_nd[idx]  = ndv;
        s_n2[idx]  = pack2(nv, nv);
        s_mr2[idx] = pack2(mr, mr);
    }
    if (t == 64) s_nin  = n_layers[b * LTOT];
    if (t == 65) s_nsub = n_layers[b * LTOT + LTOT - 1];
    __syncthreads();

    const float TWO_PI = 6.28318530717958647692f;
    const float4 lam = *reinterpret_cast<const float4*>(wavelengths + w0);
    const float k0 = __fdividef(TWO_PI, lam.x);
    const float k1 = __fdividef(TWO_PI, lam.y);
    const float k2 = __fdividef(TWO_PI, lam.z);
    const float k3 = __fdividef(TWO_PI, lam.w);

    u64 Aa = pack2(1.0f, 1.0f), Ba = 0ULL, Ca = 0ULL, Dta = pack2(-1.0f, -1.0f);
    u64 Ab = pack2(1.0f, 1.0f), Bb = 0ULL, Cb = 0ULL, Dtb = pack2(-1.0f, -1.0f);

    const int base = h * 17;
    #pragma unroll
    for (int j = 0; j < 16; ++j) {
        const float nd  = s_nd[base + j];
        const u64   n2  = s_n2[base + j];
        const u64   mr2 = s_mr2[base + j];

        // |phi| <= ~12: inside MUFU.SIN/COS accurate range (verified R2-R4)
        const float p0 = nd * k0;
        const float p1 = nd * k1;
        const float p2 = nd * k2;
        const float p3 = nd * k3;
        float s0, c0, s1, c1, s2, c2, s3, c3;
        __sincosf(p0, &s0, &c0);
        __sincosf(p1, &s1, &c1);
        __sincosf(p2, &s2, &c2);
        __sincosf(p3, &s3, &c3);

        const u64 spa = pack2(s0, s1), cpa = pack2(c0, c1);
        const u64 spb = pack2(s2, s3), cpb = pack2(c2, c3);

        const u64 nsa  = mul2(spa, n2);
        const u64 msra = mul2(spa, mr2);
        const u64 nsb  = mul2(spb, n2);
        const u64 msrb = mul2(spb, mr2);

        u64 tAa = fma2(nsa,  Ba, mul2(cpa, Aa));
        u64 tBa = fma2(msra, Aa, mul2(cpa, Ba));
        u64 tCa = fma2(nsa,  Dta, mul2(cpa, Ca));
        u64 tDa = fma2(msra, Ca,  mul2(cpa, Dta));

        u64 tAb = fma2(nsb,  Bb, mul2(cpb, Ab));
        u64 tBb = fma2(msrb, Ab, mul2(cpb, Bb));
        u64 tCb = fma2(nsb,  Dtb, mul2(cpb, Cb));
        u64 tDb = fma2(msrb, Cb,  mul2(cpb, Dtb));

        Aa = tAa; Ba = tBa; Ca = tCa; Dta = tDa;
        Ab = tAb; Bb = tBb; Cb = tCb; Dtb = tDb;
    }

    // combine the 4 layer-splits: round 0 pairs h^1 (lane^8), round 1 pairs h^2 (lane^16)
    combine(Aa, Ba, Ca, Dta, 8,  (h & 1) != 0);
    combine(Ab, Bb, Cb, Dtb, 8,  (h & 1) != 0);
    combine(Aa, Ba, Ca, Dta, 16, (h & 2) != 0);
    combine(Ab, Bb, Cb, Dtb, 16, (h & 2) != 0);

    if (h == 0) {
        const float nin  = s_nin;
        const float nsub = s_nsub;
        float R[4];
        epi2(Aa, Ba, Ca, Dta, nin, nsub, R + 0);
        epi2(Ab, Bb, Cb, Dtb, nin, nsub, R + 2);
        *reinterpret_cast<float4*>(out + b * WDIM + w0) =
            make_float4(R[0], R[1], R[2], R[3]);
    }
}

extern "C" void kernel_launch(void* const* d_in, const int* in_sizes, int n_in,
                              void* d_out, int out_size)
{
    const float* n_layers    = (const float*)d_in[0];  // (256, 64)
    const float* d_layers    = (const float*)d_in[1];  // (256, 64)
    const float* wavelengths = (const float*)d_in[2];  // (512,)
    float* out = (float*)d_out;                        // (256, 512)

    tmm_kernel<<<1024, TPB>>>(n_layers, d_layers, wavelengths, out);
}